// round 9
// baseline (speedup 1.0000x reference)
#include <cuda_runtime.h>
#include <cuda_bf16.h>
#include <cstdint>

#define NIMG 16
#define NBOX 16128
#define NCH  85
#define KSEL 500
#define KPAD 512
#define NCB  16            // 512 / 32 column blocks
#define MAXN 127           // max sparse neighbors per row (sentinel at <=127)
#define SIG_NEG4 0.017986210f   // sigmoid(-4) for zero-overlap pairs

// ---------------- device scratch (no allocations allowed) ----------------
__device__ unsigned g_sbits[NIMG * NBOX];       // packed score bits
__device__ float    g_s[NIMG][KPAD];            // sorted top scores
__device__ float4   g_box[NIMG][KPAD];          // gathered boxes
__device__ float    g_y[NIMG][KPAD];            // gathered targets
__device__ float2   g_sp[NIMG][KPAD][MAXN + 1]; // sparse {delta, col} + sentinel
__device__ float4   g_diag4[NIMG][NCB][8][32];  // diag tiles, [u][lane] = cols 4u..4u+3 of row lane
__device__ float    g_tri[NIMG][NCB][32][8];    // diag 8x8 sub-triangles
__device__ float    g_E[NIMG][KPAD];            // exp(20*v) (0 for padding)
__device__ float4   g_pair[NIMG][KPAD/2];       // per col-pair (S, P, yS, yP)
__device__ int      g_rows[NIMG][KPAD];         // compacted y=1 row indices
__device__ int      g_npos[NIMG];
__device__ float    g_c[NIMG][KPAD];            // prec*y per row

__device__ __forceinline__ float frcp(float x) {
    float r; asm("rcp.approx.f32 %0, %1;" : "=f"(r) : "f"(x)); return r;
}

// ---------------- K1: scores = max over channels 1..84 ----------------
__global__ __launch_bounds__(128) void k_scores(const float* __restrict__ preds) {
    __shared__ __align__(16) float sh[128 * NCH];
    int img = blockIdx.x / 126;
    int ch  = blockIdx.x % 126;
    size_t base = ((size_t)img * NBOX + (size_t)ch * 128) * NCH;
    const float4* src = reinterpret_cast<const float4*>(preds + base);
    float4* dst = reinterpret_cast<float4*>(sh);
    #pragma unroll 8
    for (int u = threadIdx.x; u < 128 * NCH / 4; u += 128) dst[u] = src[u];
    __syncthreads();
    int r = threadIdx.x;
    float m = sh[r * NCH + 1];
    #pragma unroll
    for (int c = 2; c < NCH; ++c) m = fmaxf(m, sh[r * NCH + c]);
    g_sbits[(size_t)img * NBOX + ch * 128 + r] = __float_as_uint(m);
}

// ---------------- K2: per-image radix select (4x8-bit) + bitonic ----------------
__global__ __launch_bounds__(512) void k_select(const float4* __restrict__ boxes,
                                                const int* __restrict__ tgt) {
    const int img = blockIdx.x;
    const int tid = threadIdx.x;
    const int w = tid >> 5, lane = tid & 31;
    __shared__ unsigned whist[16 * 256];
    __shared__ unsigned hist[256];
    __shared__ unsigned wtot[16];
    __shared__ unsigned s_bin, s_rem, s_cnt;
    __shared__ unsigned long long sbuf[1024];
    const unsigned* sb = g_sbits + (size_t)img * NBOX;

    unsigned prefix = 0;
    unsigned target = KSEL;

    #pragma unroll
    for (int pass = 0; pass < 4; ++pass) {
        const int shift = 24 - pass * 8;
        for (int u = tid; u < 4096; u += 512) whist[u] = 0;
        __syncthreads();
        for (int j = tid; j < NBOX; j += 512) {
            unsigned bits = sb[j];
            bool ok = (pass == 0) || ((bits >> (shift + 8)) == prefix);
            unsigned act = __ballot_sync(0xFFFFFFFFu, ok);
            if (ok) {
                unsigned bin = (bits >> shift) & 255u;
                unsigned mask = __match_any_sync(act, bin);
                if ((mask & ((1u << lane) - 1u)) == 0)
                    whist[w * 256 + bin] += __popc(mask);
            }
        }
        __syncthreads();
        if (tid < 256) {
            unsigned h = 0;
            #pragma unroll
            for (int ww = 0; ww < 16; ++ww) h += whist[ww * 256 + tid];
            hist[tid] = h;
        }
        __syncthreads();
        unsigned x0 = (tid < 256) ? hist[255 - tid] : 0u;
        unsigned x = x0;
        #pragma unroll
        for (int off = 1; off < 32; off <<= 1) {
            unsigned yv = __shfl_up_sync(0xFFFFFFFFu, x, off);
            if (lane >= off) x += yv;
        }
        if (lane == 31) wtot[w] = x;
        __syncthreads();
        unsigned add = 0;
        #pragma unroll
        for (int ww = 0; ww < 8; ++ww) if (ww < w) add += wtot[ww];
        unsigned inc = x + add;
        if (tid < 256 && inc >= target && (inc - x0) < target) {
            s_bin = 255u - (unsigned)tid;
            s_rem = target - (inc - x0);
        }
        __syncthreads();
        prefix = (prefix << 8) | s_bin;
        target = s_rem;
        __syncthreads();
    }
    const unsigned T = prefix;

    for (int u = tid; u < 1024; u += 512) sbuf[u] = ~0ULL;
    if (tid == 0) s_cnt = 0;
    __syncthreads();
    for (int j = tid; j < NBOX; j += 512) {
        unsigned bits = sb[j];
        if (bits >= T) {
            unsigned p = atomicAdd(&s_cnt, 1);
            if (p < 1024)
                sbuf[p] = ~(((unsigned long long)bits << 32) |
                            (unsigned long long)(0xFFFFFFFFu - (unsigned)j));
        }
    }
    __syncthreads();

    for (unsigned kk = 2; kk <= 1024; kk <<= 1) {
        for (unsigned st = kk >> 1; st > 0; st >>= 1) {
            unsigned t = (unsigned)tid;
            unsigned i = ((t & ~(st - 1)) << 1) | (t & (st - 1));
            unsigned j2 = i | st;
            bool up = ((i & kk) == 0);
            unsigned long long a = sbuf[i], b = sbuf[j2];
            if ((a > b) == up) { sbuf[i] = b; sbuf[j2] = a; }
            __syncthreads();
        }
    }

    if (tid < KSEL) {
        unsigned long long key = ~sbuf[tid];
        unsigned bits = (unsigned)(key >> 32);
        unsigned idx  = 0xFFFFFFFFu - (unsigned)(key & 0xFFFFFFFFull);
        g_s[img][tid] = __uint_as_float(bits);
        g_box[img][tid] = boxes[(size_t)img * NBOX + idx];
        g_y[img][tid] = (float)tgt[(size_t)img * NBOX + idx];
    } else {
        g_s[img][tid] = 0.f;
        g_box[img][tid] = make_float4(0.f, 0.f, 0.f, 0.f);
        g_y[img][tid] = 0.f;
    }
}

// ---------------- K3: sparse neighbor lists + diag tiles/triangles ----------------
// grid (33, NIMG) x 512. Blocks 0..31: warp-per-row sparse CSR (j < 32*(i/32)).
// Block 32: dense diag tiles + 8x8 sub-triangles.
__global__ __launch_bounds__(512) void k_sparse() {
    const int img = blockIdx.y;
    const int tid = threadIdx.x;
    const int w = tid >> 5, lane = tid & 31;
    __shared__ __align__(16) float4 bx[KPAD];
    __shared__ float ax[KPAD];

    float4 b0 = g_box[img][tid];
    bx[tid] = b0;
    ax[tid] = fmaxf(b0.z - b0.x, 0.f) * fmaxf(b0.w - b0.y, 0.f);
    __syncthreads();

    if (blockIdx.x < 32) {
        // ---- sparse lists: row i = blockIdx.x*16 + w ----
        const int i = blockIdx.x * 16 + w;
        const int nblk = i >> 5;
        float4 bi = bx[i];
        float ai = ax[i];
        int cnt = 0;
        for (int cb = 0; cb < nblk; ++cb) {
            int col = cb * 32 + lane;
            float4 bb = bx[col];
            float iw = fminf(bi.z, bb.z) - fmaxf(bi.x, bb.x);
            float ih = fminf(bi.w, bb.w) - fmaxf(bi.y, bb.y);
            bool ov = (iw > 0.f) && (ih > 0.f);
            unsigned mask = __ballot_sync(0xFFFFFFFFu, ov);
            if (mask) {
                if (ov) {
                    float inter = iw * ih;
                    float uni = ai + ax[col] - inter;
                    float iou = inter * frcp(fmaxf(uni, 1e-9f));
                    float p = frcp(1.f + __expf((0.4f - iou) * 10.f));
                    int pos = cnt + __popc(mask & ((1u << lane) - 1u));
                    if (pos < MAXN)
                        g_sp[img][i][pos] = make_float2(p - SIG_NEG4, (float)col);
                }
                cnt += __popc(mask);
            }
        }
        if (lane == 0) {
            int sp = cnt < MAXN ? cnt : MAXN;
            g_sp[img][i][sp] = make_float2(0.f, 1e9f);
        }
    } else {
        // ---- diag tiles: warp w computes tile (w,w); lane = row within tile ----
        float4 bi = bx[tid];
        float ai = ax[tid];
        float out[32];
        #pragma unroll
        for (int c = 0; c < 32; ++c) {
            int col = w * 32 + c;
            float4 bb = bx[col];
            float iw = fminf(bi.z, bb.z) - fmaxf(bi.x, bb.x);
            float ih = fminf(bi.w, bb.w) - fmaxf(bi.y, bb.y);
            bool ov = (iw > 0.f) && (ih > 0.f);
            float p;
            if (__any_sync(0xFFFFFFFFu, ov)) {
                float inter = fmaxf(iw, 0.f) * fmaxf(ih, 0.f);
                float uni = ai + ax[col] - inter;
                float iou = inter * frcp(fmaxf(uni, 1e-9f));
                p = frcp(1.f + __expf((0.4f - iou) * 10.f));
            } else {
                p = SIG_NEG4;
            }
            out[c] = p;
        }
        #pragma unroll
        for (int u = 0; u < 8; ++u)
            g_diag4[img][w][u][lane] =
                make_float4(out[4*u], out[4*u+1], out[4*u+2], out[4*u+3]);
        const int q = lane >> 3, k = lane & 7;
        #pragma unroll
        for (int j = 0; j < 7; ++j)
            if (j < k) g_tri[img][w][lane][j] = out[q * 8 + j];
    }
}

// ---------------- K4: soft-NMS — sparse + block-sum rank-1, no dense GEMV ----------------
__global__ __launch_bounds__(512) void k_nms() {
    const int img = blockIdx.x;
    const int tid = threadIdx.x;
    const int w = tid >> 5, lane = tid & 31;
    __shared__ __align__(16) float vsh[KPAD];
    __shared__ float tri[NCB][32][8];
    __shared__ float bsum[NCB];
    __shared__ int wcnt[NCB];

    // own diag tile row -> registers (coalesced via transposed layout)
    float pc[32];
    #pragma unroll
    for (int u = 0; u < 8; ++u) {
        float4 L = g_diag4[img][w][u][lane];
        pc[4*u+0] = L.x; pc[4*u+1] = L.y; pc[4*u+2] = L.z; pc[4*u+3] = L.w;
    }
    // own triangle -> shared
    {
        const float4* src = reinterpret_cast<const float4*>(&g_tri[img][w][0][0]);
        float4* dst = reinterpret_cast<float4*>(&tri[w][0][0]);
        dst[lane] = src[lane];
        dst[lane + 32] = src[lane + 32];
    }
    const float2* sp = &g_sp[img][tid][0];
    float2 e = sp[0];
    int ptr = 0;
    float rr = g_s[img][tid];
    __syncwarp();

    const float (*tw)[8] = tri[w];
    for (int cb = 0; cb < NCB; ++cb) {
        if (w == cb) {
            float bsv = 0.f;
            #pragma unroll
            for (int q = 0; q < 4; ++q) {
                const int base = q * 8;
                float a0 = __shfl_sync(0xFFFFFFFFu, rr, base + 0);
                float a1 = __shfl_sync(0xFFFFFFFFu, rr, base + 1);
                float a2 = __shfl_sync(0xFFFFFFFFu, rr, base + 2);
                float a3 = __shfl_sync(0xFFFFFFFFu, rr, base + 3);
                float a4 = __shfl_sync(0xFFFFFFFFu, rr, base + 4);
                float a5 = __shfl_sync(0xFFFFFFFFu, rr, base + 5);
                float a6 = __shfl_sync(0xFFFFFFFFu, rr, base + 6);
                float a7 = __shfl_sync(0xFFFFFFFFu, rr, base + 7);
                float v0 = fmaxf(a0, 0.f);
                a1 = fmaf(-tw[base+1][0], v0, a1);  float v1 = fmaxf(a1, 0.f);
                a2 = fmaf(-tw[base+2][0], v0, a2);  a2 = fmaf(-tw[base+2][1], v1, a2);
                float v2 = fmaxf(a2, 0.f);
                a3 = fmaf(-tw[base+3][0], v0, a3);  a3 = fmaf(-tw[base+3][1], v1, a3);
                a3 = fmaf(-tw[base+3][2], v2, a3);  float v3 = fmaxf(a3, 0.f);
                a4 = fmaf(-tw[base+4][0], v0, a4);  a4 = fmaf(-tw[base+4][1], v1, a4);
                a4 = fmaf(-tw[base+4][2], v2, a4);  a4 = fmaf(-tw[base+4][3], v3, a4);
                float v4 = fmaxf(a4, 0.f);
                a5 = fmaf(-tw[base+5][0], v0, a5);  a5 = fmaf(-tw[base+5][1], v1, a5);
                a5 = fmaf(-tw[base+5][2], v2, a5);  a5 = fmaf(-tw[base+5][3], v3, a5);
                a5 = fmaf(-tw[base+5][4], v4, a5);  float v5 = fmaxf(a5, 0.f);
                a6 = fmaf(-tw[base+6][0], v0, a6);  a6 = fmaf(-tw[base+6][1], v1, a6);
                a6 = fmaf(-tw[base+6][2], v2, a6);  a6 = fmaf(-tw[base+6][3], v3, a6);
                a6 = fmaf(-tw[base+6][4], v4, a6);  a6 = fmaf(-tw[base+6][5], v5, a6);
                float v6 = fmaxf(a6, 0.f);
                a7 = fmaf(-tw[base+7][0], v0, a7);  a7 = fmaf(-tw[base+7][1], v1, a7);
                a7 = fmaf(-tw[base+7][2], v2, a7);  a7 = fmaf(-tw[base+7][3], v3, a7);
                a7 = fmaf(-tw[base+7][4], v4, a7);  a7 = fmaf(-tw[base+7][5], v5, a7);
                a7 = fmaf(-tw[base+7][6], v6, a7);  float v7 = fmaxf(a7, 0.f);
                if (lane == base + 0) vsh[tid] = v0;
                if (lane == base + 1) vsh[tid] = v1;
                if (lane == base + 2) vsh[tid] = v2;
                if (lane == base + 3) vsh[tid] = v3;
                if (lane == base + 4) vsh[tid] = v4;
                if (lane == base + 5) vsh[tid] = v5;
                if (lane == base + 6) vsh[tid] = v6;
                if (lane == base + 7) vsh[tid] = v7;
                float m01 = pc[base + 0] * v0; m01 = fmaf(pc[base + 1], v1, m01);
                float m23 = pc[base + 2] * v2; m23 = fmaf(pc[base + 3], v3, m23);
                float m45 = pc[base + 4] * v4; m45 = fmaf(pc[base + 5], v5, m45);
                float m67 = pc[base + 6] * v6; m67 = fmaf(pc[base + 7], v7, m67);
                rr = rr - ((m01 + m23) + (m45 + m67));
                bsv += ((v0 + v1) + (v2 + v3)) + ((v4 + v5) + (v6 + v7));
            }
            if (lane == 0) bsum[cb] = bsv;
        }
        __syncthreads();
        if (w > cb) {
            rr = fmaf(-SIG_NEG4, bsum[cb], rr);
            float blockend = (float)((cb + 1) * 32);
            while (e.y < blockend) {
                rr = fmaf(-e.x, vsh[(int)e.y], rr);
                e = sp[++ptr];
            }
        }
    }

    // ---- epilogue: E, pair constants, positive-row compaction ----
    float v = vsh[tid];
    bool valid = tid < KSEL;
    float E = valid ? __expf(20.f * v) : 0.f;
    float y = valid ? g_y[img][tid] : 0.f;
    g_E[img][tid] = E;
    g_c[img][tid] = 0.f;

    float Eb = __shfl_down_sync(0xFFFFFFFFu, E, 1);
    float yb = __shfl_down_sync(0xFFFFFFFFu, y, 1);
    if (!(lane & 1)) {
        float S = E + Eb;
        float P = E * Eb;
        float yS = fmaf(y, E, yb * Eb);
        float yP = (y + yb) * P;
        g_pair[img][tid >> 1] = make_float4(S, P, yS, yP);
    }

    bool pos = valid && (y != 0.f);
    unsigned vote = __ballot_sync(0xFFFFFFFFu, pos);
    if (lane == 0) wcnt[w] = __popc(vote);
    __syncthreads();
    int base2 = 0;
    #pragma unroll
    for (int ww = 0; ww < NCB; ++ww) if (ww < w) base2 += wcnt[ww];
    if (pos) {
        int off = __popc(vote & ((1u << lane) - 1u));
        g_rows[img][base2 + off] = tid;
    }
    if (tid == 0) {
        int tot = 0;
        #pragma unroll
        for (int ww = 0; ww < NCB; ++ww) tot += wcnt[ww];
        g_npos[img] = tot;
    }
}

// ---------------- K5: ap_loss — one warp per positive row, paired columns ----------------
__global__ __launch_bounds__(256) void k_ap() {
    const int img = blockIdx.y;
    const int wid = threadIdx.x >> 5, lane = threadIdx.x & 31;
    const int slot = blockIdx.x * 8 + wid;
    if (slot >= g_npos[img]) return;
    const int i = g_rows[img][slot];
    const float Ei = g_E[img][i];
    const float4* pr = g_pair[img];
    float sh = 0.f, shy = 0.f;
    #pragma unroll
    for (int u = 0; u < 8; ++u) {
        float4 q = pr[u * 32 + lane];
        float t = fmaf(Ei, q.x, q.y);
        float num = t + q.y;
        float den = fmaf(Ei, Ei, t);
        float rr = frcp(den);
        sh = fmaf(num, rr, sh);
        float numy = fmaf(Ei, q.z, q.w);
        shy = fmaf(numy, rr, shy);
    }
    #pragma unroll
    for (int off = 16; off > 0; off >>= 1) {
        sh  += __shfl_down_sync(0xFFFFFFFFu, sh, off);
        shy += __shfl_down_sync(0xFFFFFFFFu, shy, off);
    }
    if (lane == 0) g_c[img][i] = __fdividef(0.5f + shy, 0.5f + sh);
}

// ---------------- K6: warp-per-image final reduction ----------------
__global__ __launch_bounds__(512) void k_final(float* __restrict__ out) {
    const int w = threadIdx.x >> 5, lane = threadIdx.x & 31;
    __shared__ float part[16];
    float sc = 0.f, sy = 0.f;
    #pragma unroll
    for (int u = lane; u < KPAD; u += 32) {
        sc += g_c[w][u];
        sy += g_y[w][u];
    }
    #pragma unroll
    for (int off = 16; off > 0; off >>= 1) {
        sc += __shfl_down_sync(0xFFFFFFFFu, sc, off);
        sy += __shfl_down_sync(0xFFFFFFFFu, sy, off);
    }
    if (lane == 0) part[w] = 1.f - sc / fmaxf(sy, 1.f);
    __syncthreads();
    if (threadIdx.x == 0) {
        float t = 0.f;
        #pragma unroll
        for (int k = 0; k < NIMG; ++k) t += part[k];
        out[0] = t / (float)NIMG;
    }
}

// ---------------- driver ----------------
extern "C" void kernel_launch(void* const* d_in, const int* in_sizes, int n_in,
                              void* d_out, int out_size) {
    const float* preds = nullptr;
    const float* boxes = nullptr;
    const int*   targets = nullptr;
    for (int i = 0; i < n_in; ++i) {
        long sz = in_sizes[i];
        if (sz == (long)NIMG * NBOX * NCH) preds = (const float*)d_in[i];
        else if (sz == (long)NIMG * NBOX * 4) boxes = (const float*)d_in[i];
        else if (sz == (long)NIMG * NBOX) targets = (const int*)d_in[i];
    }
    if (!preds)   preds   = (const float*)d_in[0];
    if (!boxes)   boxes   = (const float*)d_in[1];
    if (!targets) targets = (const int*)d_in[2];

    k_scores<<<NIMG * 126, 128>>>(preds);
    k_select<<<NIMG, 512>>>(reinterpret_cast<const float4*>(boxes), targets);
    k_sparse<<<dim3(33, NIMG), 512>>>();
    k_nms<<<NIMG, 512>>>();
    k_ap<<<dim3(64, NIMG), 256>>>();
    k_final<<<1, 512>>>((float*)d_out);
}

// round 10
// speedup vs baseline: 1.5159x; 1.5159x over previous
#include <cuda_runtime.h>
#include <cuda_bf16.h>
#include <cstdint>

#define NIMG 16
#define NBOX 16128
#define NCH  85
#define KSEL 500
#define KPAD 512
#define NCB  16            // 512 / 32 column blocks
#define SIG_NEG4 0.017986210f   // sigmoid(-4) for zero-overlap pairs

// ---------------- device scratch (no allocations allowed) ----------------
__device__ unsigned g_sbits[NIMG * NBOX];                 // packed score bits
__device__ float    g_s[NIMG][KPAD];                      // sorted top scores
__device__ float4   g_box[NIMG][KPAD];                    // gathered boxes
__device__ float    g_y[NIMG][KPAD];                      // gathered targets
__device__ float    g_pT[NIMG][NCB][32][KPAD];            // prune TRANSPOSED [img][cb][t][row]
__device__ float    g_E[NIMG][KPAD];                      // exp(20*v) (0 for padding)
__device__ float4   g_pair[NIMG][KPAD/2];                 // per col-pair (S, P, yS, yP)
__device__ int      g_rows[NIMG][KPAD];                   // compacted y=1 row indices
__device__ int      g_npos[NIMG];
__device__ float    g_c[NIMG][KPAD];                      // prec*y per row

__device__ __forceinline__ float frcp(float x) {
    float r; asm("rcp.approx.f32 %0, %1;" : "=f"(r) : "f"(x)); return r;
}

// ---------------- K1: scores = max over channels 1..84 ----------------
__global__ __launch_bounds__(128) void k_scores(const float* __restrict__ preds) {
    __shared__ __align__(16) float sh[128 * NCH];
    int img = blockIdx.x / 126;
    int ch  = blockIdx.x % 126;
    size_t base = ((size_t)img * NBOX + (size_t)ch * 128) * NCH;
    const float4* src = reinterpret_cast<const float4*>(preds + base);
    float4* dst = reinterpret_cast<float4*>(sh);
    #pragma unroll 8
    for (int u = threadIdx.x; u < 128 * NCH / 4; u += 128) dst[u] = src[u];
    __syncthreads();
    int r = threadIdx.x;
    float m = sh[r * NCH + 1];
    #pragma unroll
    for (int c = 2; c < NCH; ++c) m = fmaxf(m, sh[r * NCH + c]);
    g_sbits[(size_t)img * NBOX + ch * 128 + r] = __float_as_uint(m);
}

// ---------------- K2: per-image radix select (4x8-bit) + bitonic ----------------
__global__ __launch_bounds__(512) void k_select(const float4* __restrict__ boxes,
                                                const int* __restrict__ tgt) {
    const int img = blockIdx.x;
    const int tid = threadIdx.x;
    const int w = tid >> 5, lane = tid & 31;
    __shared__ unsigned whist[16 * 256];
    __shared__ unsigned hist[256];
    __shared__ unsigned wtot[16];
    __shared__ unsigned s_bin, s_rem, s_cnt;
    __shared__ unsigned long long sbuf[1024];
    const unsigned* sb = g_sbits + (size_t)img * NBOX;

    unsigned prefix = 0;
    unsigned target = KSEL;

    #pragma unroll
    for (int pass = 0; pass < 4; ++pass) {
        const int shift = 24 - pass * 8;
        for (int u = tid; u < 4096; u += 512) whist[u] = 0;
        __syncthreads();
        for (int j = tid; j < NBOX; j += 512) {
            unsigned bits = sb[j];
            bool ok = (pass == 0) || ((bits >> (shift + 8)) == prefix);
            unsigned act = __ballot_sync(0xFFFFFFFFu, ok);
            if (ok) {
                unsigned bin = (bits >> shift) & 255u;
                unsigned mask = __match_any_sync(act, bin);
                if ((mask & ((1u << lane) - 1u)) == 0)
                    whist[w * 256 + bin] += __popc(mask);
            }
        }
        __syncthreads();
        if (tid < 256) {
            unsigned h = 0;
            #pragma unroll
            for (int ww = 0; ww < 16; ++ww) h += whist[ww * 256 + tid];
            hist[tid] = h;
        }
        __syncthreads();
        unsigned x0 = (tid < 256) ? hist[255 - tid] : 0u;
        unsigned x = x0;
        #pragma unroll
        for (int off = 1; off < 32; off <<= 1) {
            unsigned yv = __shfl_up_sync(0xFFFFFFFFu, x, off);
            if (lane >= off) x += yv;
        }
        if (lane == 31) wtot[w] = x;
        __syncthreads();
        unsigned add = 0;
        #pragma unroll
        for (int ww = 0; ww < 8; ++ww) if (ww < w) add += wtot[ww];
        unsigned inc = x + add;
        if (tid < 256 && inc >= target && (inc - x0) < target) {
            s_bin = 255u - (unsigned)tid;
            s_rem = target - (inc - x0);
        }
        __syncthreads();
        prefix = (prefix << 8) | s_bin;
        target = s_rem;
        __syncthreads();
    }
    const unsigned T = prefix;

    for (int u = tid; u < 1024; u += 512) sbuf[u] = ~0ULL;
    if (tid == 0) s_cnt = 0;
    __syncthreads();
    for (int j = tid; j < NBOX; j += 512) {
        unsigned bits = sb[j];
        if (bits >= T) {
            unsigned p = atomicAdd(&s_cnt, 1);
            if (p < 1024)
                sbuf[p] = ~(((unsigned long long)bits << 32) |
                            (unsigned long long)(0xFFFFFFFFu - (unsigned)j));
        }
    }
    __syncthreads();

    for (unsigned kk = 2; kk <= 1024; kk <<= 1) {
        for (unsigned st = kk >> 1; st > 0; st >>= 1) {
            unsigned t = (unsigned)tid;
            unsigned i = ((t & ~(st - 1)) << 1) | (t & (st - 1));
            unsigned j2 = i | st;
            bool up = ((i & kk) == 0);
            unsigned long long a = sbuf[i], b = sbuf[j2];
            if ((a > b) == up) { sbuf[i] = b; sbuf[j2] = a; }
            __syncthreads();
        }
    }

    if (tid < KSEL) {
        unsigned long long key = ~sbuf[tid];
        unsigned bits = (unsigned)(key >> 32);
        unsigned idx  = 0xFFFFFFFFu - (unsigned)(key & 0xFFFFFFFFull);
        g_s[img][tid] = __uint_as_float(bits);
        g_box[img][tid] = boxes[(size_t)img * NBOX + idx];
        g_y[img][tid] = (float)tgt[(size_t)img * NBOX + idx];
    } else {
        g_s[img][tid] = 0.f;
        g_box[img][tid] = make_float4(0.f, 0.f, 0.f, 0.f);
        g_y[img][tid] = 0.f;
    }
}

// ---------------- K3: prune matrix, triangle tiles only, TRANSPOSED store ----------------
// grid (34, NIMG) x 128: 4 warps/block, one 32x32 tile per warp, 136 tiles/img.
__global__ __launch_bounds__(128) void k_prune() {
    const int img = blockIdx.y;
    const int w = threadIdx.x >> 5, lane = threadIdx.x & 31;
    const int t = blockIdx.x * 4 + w;                 // tile id, 0..135
    __shared__ float4 sbj[4][32];
    __shared__ float  saj[4][32];

    int rb = (int)((sqrtf(8.f * (float)t + 1.f) - 1.f) * 0.5f);
    if ((rb + 1) * (rb + 2) / 2 <= t) rb++;
    if (rb * (rb + 1) / 2 > t) rb--;
    const int cb = t - rb * (rb + 1) / 2;

    {
        float4 b = g_box[img][cb * 32 + lane];
        sbj[w][lane] = b;
        saj[w][lane] = fmaxf(b.z - b.x, 0.f) * fmaxf(b.w - b.y, 0.f);
    }
    __syncwarp();

    const int i = rb * 32 + lane;
    float4 bi = g_box[img][i];
    float ai = fmaxf(bi.z - bi.x, 0.f) * fmaxf(bi.w - bi.y, 0.f);
    #pragma unroll
    for (int c = 0; c < 32; ++c) {
        float4 bb = sbj[w][c];
        float iw = fminf(bi.z, bb.z) - fmaxf(bi.x, bb.x);
        float ih = fminf(bi.w, bb.w) - fmaxf(bi.y, bb.y);
        bool ov = (iw > 0.f) && (ih > 0.f);
        float p;
        if (__any_sync(0xFFFFFFFFu, ov)) {
            float inter = fmaxf(iw, 0.f) * fmaxf(ih, 0.f);
            float uni = ai + saj[w][c] - inter;
            float iou = inter * frcp(fmaxf(uni, 1e-9f));
            p = frcp(1.f + __expf((0.4f - iou) * 10.f));
        } else {
            p = SIG_NEG4;
        }
        g_pT[img][cb][c][i] = p;      // transposed: coalesced across lanes
    }
}

// ---------------- K4: soft-NMS — R2 body, coalesced transposed loads ----------------
__global__ __launch_bounds__(512) void k_nms() {
    const int img = blockIdx.x;
    const int tid = threadIdx.x;
    const int w = tid >> 5, lane = tid & 31;
    __shared__ __align__(16) float vsh[KPAD];
    __shared__ int wcnt[NCB];
    const float* pT = &g_pT[img][0][0][0];       // [cb][t][row], row stride KPAD

    float cur[32], nxt[32];
    #pragma unroll
    for (int u = 0; u < 32; ++u) cur[u] = pT[u * KPAD + tid];   // tile 0, coalesced

    float s = g_s[img][tid];
    float acc = 0.f;
    for (int cb = 0; cb < NCB; ++cb) {
        if (cb < NCB - 1 && w >= cb + 1) {       // prefetch next tile (coalesced scalar LDGs)
            const float* nb = pT + (size_t)(cb + 1) * 32 * KPAD;
            #pragma unroll
            for (int u = 0; u < 32; ++u) nxt[u] = nb[u * KPAD + tid];
        }
        if (w == cb) {
            // serial resolution of 32 diagonal columns via shfl chain
            float rr = s - acc;
            #pragma unroll
            for (int m = 0; m < 32; ++m) {
                float vm = __shfl_sync(0xFFFFFFFFu, fmaxf(rr, 0.f), m);
                if (lane == m) vsh[tid] = vm;
                if (lane > m) rr = fmaf(-cur[m], vm, rr);
            }
        }
        __syncthreads();
        if (w > cb) {
            const float4* vv = reinterpret_cast<const float4*>(&vsh[cb * 32]);
            #pragma unroll
            for (int u = 0; u < 8; ++u) {
                float4 v4 = vv[u];
                acc = fmaf(cur[4*u+0], v4.x, acc);
                acc = fmaf(cur[4*u+1], v4.y, acc);
                acc = fmaf(cur[4*u+2], v4.z, acc);
                acc = fmaf(cur[4*u+3], v4.w, acc);
            }
        }
        #pragma unroll
        for (int u = 0; u < 32; ++u) cur[u] = nxt[u];
    }
    __syncthreads();

    // ---- epilogue: E, pair constants, positive-row compaction ----
    float v = vsh[tid];
    bool valid = tid < KSEL;
    float E = valid ? __expf(20.f * v) : 0.f;
    float y = valid ? g_y[img][tid] : 0.f;
    g_E[img][tid] = E;
    g_c[img][tid] = 0.f;

    float Eb = __shfl_down_sync(0xFFFFFFFFu, E, 1);
    float yb = __shfl_down_sync(0xFFFFFFFFu, y, 1);
    if (!(lane & 1)) {
        float S = E + Eb;
        float P = E * Eb;
        float yS = fmaf(y, E, yb * Eb);
        float yP = (y + yb) * P;
        g_pair[img][tid >> 1] = make_float4(S, P, yS, yP);
    }

    bool pos = valid && (y != 0.f);
    unsigned vote = __ballot_sync(0xFFFFFFFFu, pos);
    if (lane == 0) wcnt[w] = __popc(vote);
    __syncthreads();
    int base = 0;
    #pragma unroll
    for (int ww = 0; ww < NCB; ++ww) if (ww < w) base += wcnt[ww];
    if (pos) {
        int off = __popc(vote & ((1u << lane) - 1u));
        g_rows[img][base + off] = tid;
    }
    if (tid == 0) {
        int tot = 0;
        #pragma unroll
        for (int ww = 0; ww < NCB; ++ww) tot += wcnt[ww];
        g_npos[img] = tot;
    }
}

// ---------------- K5: ap_loss — one warp per positive row, paired columns ----------------
// h_ia + h_ib = (Ei*S + 2P) / (Ei^2 + Ei*S + P): 1 rcp per 2 columns (exact algebra)
__global__ __launch_bounds__(256) void k_ap() {
    const int img = blockIdx.y;
    const int wid = threadIdx.x >> 5, lane = threadIdx.x & 31;
    const int slot = blockIdx.x * 8 + wid;
    if (slot >= g_npos[img]) return;     // uniform per warp
    const int i = g_rows[img][slot];
    const float Ei = g_E[img][i];
    const float4* pr = g_pair[img];
    float sh = 0.f, shy = 0.f;
    #pragma unroll
    for (int u = 0; u < 8; ++u) {
        float4 q = pr[u * 32 + lane];
        float t = fmaf(Ei, q.x, q.y);       // Ei*S + P
        float num = t + q.y;                // Ei*S + 2P
        float den = fmaf(Ei, Ei, t);        // Ei^2 + Ei*S + P
        float rr = frcp(den);
        sh = fmaf(num, rr, sh);
        float numy = fmaf(Ei, q.z, q.w);    // Ei*yS + yP
        shy = fmaf(numy, rr, shy);
    }
    #pragma unroll
    for (int off = 16; off > 0; off >>= 1) {
        sh  += __shfl_down_sync(0xFFFFFFFFu, sh, off);
        shy += __shfl_down_sync(0xFFFFFFFFu, shy, off);
    }
    // sums include self-pair exactly as h_ii = 0.5
    if (lane == 0) g_c[img][i] = __fdividef(0.5f + shy, 0.5f + sh);
}

// ---------------- K6: warp-per-image final reduction ----------------
__global__ __launch_bounds__(512) void k_final(float* __restrict__ out) {
    const int w = threadIdx.x >> 5, lane = threadIdx.x & 31;
    __shared__ float part[16];
    float sc = 0.f, sy = 0.f;
    #pragma unroll
    for (int u = lane; u < KPAD; u += 32) {
        sc += g_c[w][u];
        sy += g_y[w][u];
    }
    #pragma unroll
    for (int off = 16; off > 0; off >>= 1) {
        sc += __shfl_down_sync(0xFFFFFFFFu, sc, off);
        sy += __shfl_down_sync(0xFFFFFFFFu, sy, off);
    }
    if (lane == 0) part[w] = 1.f - sc / fmaxf(sy, 1.f);
    __syncthreads();
    if (threadIdx.x == 0) {
        float t = 0.f;
        #pragma unroll
        for (int k = 0; k < NIMG; ++k) t += part[k];
        out[0] = t / (float)NIMG;
    }
}

// ---------------- driver ----------------
extern "C" void kernel_launch(void* const* d_in, const int* in_sizes, int n_in,
                              void* d_out, int out_size) {
    const float* preds = nullptr;
    const float* boxes = nullptr;
    const int*   targets = nullptr;
    for (int i = 0; i < n_in; ++i) {
        long sz = in_sizes[i];
        if (sz == (long)NIMG * NBOX * NCH) preds = (const float*)d_in[i];
        else if (sz == (long)NIMG * NBOX * 4) boxes = (const float*)d_in[i];
        else if (sz == (long)NIMG * NBOX) targets = (const int*)d_in[i];
    }
    if (!preds)   preds   = (const float*)d_in[0];
    if (!boxes)   boxes   = (const float*)d_in[1];
    if (!targets) targets = (const int*)d_in[2];

    k_scores<<<NIMG * 126, 128>>>(preds);
    k_select<<<NIMG, 512>>>(reinterpret_cast<const float4*>(boxes), targets);
    k_prune<<<dim3(34, NIMG), 128>>>();
    k_nms<<<NIMG, 512>>>();
    k_ap<<<dim3(64, NIMG), 256>>>();
    k_final<<<1, 512>>>((float*)d_out);
}